// round 16
// baseline (speedup 1.0000x reference)
#include <cuda_runtime.h>
#include <cuda_fp16.h>
#include <math.h>

// Problem constants
#define BB     64
#define TT     2048
#define DD     40
#define HH     164
#define HP     192            // padded hidden (6 CTAs x 32 j)
#define XP     48             // padded x dim (l0)
#define NOUT   7
#define NCOL   6              // CTAs per layer = cluster size
#define NLAYER 3
#define NCTA   (NCOL * NLAYER) // 18
#define TB     256             // 8 warps
#define RS     4               // g_h ring depth (cross-layer)
#define NSLOT  8
#define AS     392             // A row stride (halves)
#define BS     72              // B row stride (halves)
#define HXTX   24576           // DSMEM tx bytes per phase: 6 CTAs * 32j * 64b * 2B

// ---- smem layout (bytes) ----
#define OFF_A   0                          // weights fp16 [128][392] = 100352
#define OFF_X   100352                     // x/producer rows [192][72] = 27648
#define OFF_H0  128000                     // own-h buffer 0 [192][72] = 27648
#define OFF_H1  155648                     // own-h buffer 1 = 27648
#define OFF_G   183296                     // gates f32 [128][68] = 34816
#define OFF_C   218112                     // cell f32 [32][64] = 8192
#define OFF_BI  226304                     // bias f32 [128] = 512
#define OFF_LEN 226816                     // lengths = 256
#define OFF_MB  227072                     // 2 mbarriers = 16
#define SMEM_BYTES 227104

// ---------------- device scratch ----------------
__device__ __align__(256) __half g_xTh[TT * XP * BB];          // x fp16: [t][d48][b]
__device__ __align__(256) __half g_h[NLAYER * RS * HP * BB];   // cross-layer h: [l][slot][j][b]
__device__ unsigned g_flag[NCTA * 32];
__device__ __align__(128) unsigned g_cnt[NLAYER * NSLOT * 32];

// ---------------- helpers ----------------
__device__ __forceinline__ unsigned smem_u32(const void* p) {
    return (unsigned)__cvta_generic_to_shared(p);
}
__device__ __forceinline__ void ldsm_x4(unsigned& r0, unsigned& r1, unsigned& r2, unsigned& r3,
                                        unsigned addr) {
    asm volatile("ldmatrix.sync.aligned.m8n8.x4.shared.b16 {%0,%1,%2,%3}, [%4];"
                 : "=r"(r0), "=r"(r1), "=r"(r2), "=r"(r3) : "r"(addr));
}
__device__ __forceinline__ void ldsm_x4t(unsigned& r0, unsigned& r1, unsigned& r2, unsigned& r3,
                                         unsigned addr) {
    asm volatile("ldmatrix.sync.aligned.m8n8.x4.trans.shared.b16 {%0,%1,%2,%3}, [%4];"
                 : "=r"(r0), "=r"(r1), "=r"(r2), "=r"(r3) : "r"(addr));
}
__device__ __forceinline__ void mma16816(float* d, unsigned a0, unsigned a1, unsigned a2,
                                         unsigned a3, unsigned b0, unsigned b1) {
    asm volatile("mma.sync.aligned.m16n8k16.row.col.f32.f16.f16.f32 "
                 "{%0,%1,%2,%3}, {%4,%5,%6,%7}, {%8,%9}, {%0,%1,%2,%3};"
                 : "+f"(d[0]), "+f"(d[1]), "+f"(d[2]), "+f"(d[3])
                 : "r"(a0), "r"(a1), "r"(a2), "r"(a3), "r"(b0), "r"(b1));
}
__device__ __forceinline__ void cp16(unsigned dst_smem, const void* src) {
    asm volatile("cp.async.cg.shared.global [%0], [%1], 16;" :: "r"(dst_smem), "l"(src));
}
__device__ __forceinline__ void mbar_init(unsigned addr, unsigned cnt) {
    asm volatile("mbarrier.init.shared.b64 [%0], %1;" :: "r"(addr), "r"(cnt) : "memory");
}
__device__ __forceinline__ void mbar_expect_tx(unsigned addr, unsigned bytes) {
    asm volatile("mbarrier.arrive.expect_tx.shared.b64 _, [%0], %1;" :: "r"(addr), "r"(bytes) : "memory");
}
__device__ __forceinline__ void mbar_wait(unsigned addr, unsigned parity) {
    asm volatile(
        "{\n\t.reg .pred P1;\n\t"
        "W_%=:\n\t"
        "mbarrier.try_wait.parity.acquire.cta.shared::cta.b64 P1, [%0], %1, 0x989680;\n\t"
        "@P1 bra D_%=;\n\tbra W_%=;\n\tD_%=:\n\t}"
        :: "r"(addr), "r"(parity) : "memory");
}
__device__ __forceinline__ unsigned mapa_sh(unsigned laddr, unsigned rank) {
    unsigned r;
    asm("mapa.shared::cluster.u32 %0, %1, %2;" : "=r"(r) : "r"(laddr), "r"(rank));
    return r;
}
__device__ __forceinline__ void st_async64(unsigned raddr, unsigned long long v, unsigned rmbar) {
    asm volatile("st.async.shared::cluster.mbarrier::complete_tx::bytes.b64 [%0], %1, [%2];"
                 :: "r"(raddr), "l"(v), "r"(rmbar) : "memory");
}
__device__ __forceinline__ unsigned flag_acq(const unsigned* p) {
    unsigned r;
    asm volatile("ld.global.acquire.gpu.u32 %0, [%1];" : "=r"(r) : "l"(p));
    return r;
}
__device__ __forceinline__ void flag_rel(unsigned* p, unsigned v) {
    asm volatile("st.global.release.gpu.u32 [%0], %1;" :: "l"(p), "r"(v) : "memory");
}
__device__ __forceinline__ void cnt_add(unsigned* p) {
    asm volatile("red.release.gpu.global.add.u32 [%0], 1;" :: "l"(p) : "memory");
}
__device__ __forceinline__ void cnt_poll(const unsigned* p, unsigned tgt) {
    while (flag_acq(p) < tgt) { }
}
__device__ __forceinline__ unsigned cnt_tgt(int v) {
    return (unsigned)NCOL * ((unsigned)(v >> 3) + 1u);
}
__device__ __forceinline__ float sigf(float x) {          // proven R14 path (__expf MUFU)
    float e = __expf(-x);
    return __fdividef(1.f, 1.f + e);
}
__device__ __forceinline__ float tanhfast(float z) {
    float e = __expf(-2.f * z);
    return __fdividef(2.f, 1.f + e) - 1.f;
}

// ---------------- persistent HMMA + DSMEM LSTM ----------------
__global__ void __launch_bounds__(TB, 1) __cluster_dims__(NCOL, 1, 1) k_lstm(
    const float* __restrict__ x,
    const int*   __restrict__ lengths,
    const float* __restrict__ Wih0, const float* __restrict__ Whh0, const float* __restrict__ bb0,
    const float* __restrict__ Wih1, const float* __restrict__ Whh1, const float* __restrict__ bb1,
    const float* __restrict__ Wih2, const float* __restrict__ Whh2, const float* __restrict__ bb2,
    const float* __restrict__ fcw,  const float* __restrict__ fcb,
    float* __restrict__ out)
{
    extern __shared__ char smem[];
    const unsigned smb = smem_u32(smem);
    __half* sA  = (__half*)(smem + OFF_A);
    float*  sG  = (float*)(smem + OFF_G);
    float*  sC  = (float*)(smem + OFF_C);
    float*  sBi = (float*)(smem + OFF_BI);
    int*    sLen= (int*)  (smem + OFF_LEN);

    const int tid  = threadIdx.x;
    const int cta  = blockIdx.x;
    const int l    = cta / NCOL;
    const int cb   = cta - l * NCOL;
    const int j0   = cb * 32;
    const int wid  = tid >> 5;
    const int lane = tid & 31;

    const unsigned base = g_flag[cta * 32];

    const float *Wih, *Whh, *bias;
    int KX;
    if (l == 0)      { Wih = Wih0; Whh = Whh0; bias = bb0; KX = XP; }
    else if (l == 1) { Wih = Wih1; Whh = Whh1; bias = bb1; KX = HP; }
    else             { Wih = Wih2; Whh = Whh2; bias = bb2; KX = HP; }
    const int K   = KX + HP;        // 240 or 384
    const int KC  = K >> 4;         // 15 or 24
    const int KXc = KX >> 4;        // 3 or 12

    // ---------- Phase A ----------
    for (int m = 0; m < 128; ++m) {
        int g = m >> 5, jj = m & 31, j = j0 + jj;
        for (int k = tid; k < K; k += TB) {
            float w = 0.f;
            if (j < HH) {
                if (k < KX) {
                    if (l == 0) { if (k < DD) w = Wih[(g * HH + j) * DD + k]; }
                    else        { if (k < HH) w = Wih[(g * HH + j) * HH + k]; }
                } else {
                    int kk = k - KX;
                    if (kk < HH) w = Whh[(g * HH + j) * HH + kk];
                }
            }
            sA[m * AS + k] = __float2half_rn(w);
        }
    }
    if (tid < 128) {
        int g = tid >> 5, jj = tid & 31, j = j0 + jj;
        sBi[tid] = (j < HH) ? bias[g * HH + j] : 0.f;
    }
    if (tid < BB) sLen[tid] = lengths[tid];
    for (int i = tid; i < 32 * BB; i += TB) sC[i] = 0.f;
    // zero both own-h smem buffers
    for (int i = tid; i < (2 * HP * BS) / 2; i += TB)
        ((unsigned*)(smem + OFF_H0))[i] = 0u;
    if (tid == 0) {
        mbar_init(smb + OFF_MB + 0, 1);
        mbar_init(smb + OFF_MB + 8, 1);
    }
    if (cta == 0 && tid < NLAYER * NSLOT) g_cnt[tid * 32] = 0u;
    {
        unsigned* gh32 = (unsigned*)g_h;
        const int NH = (NLAYER * RS * HP * BB) / 2;
        for (int i = cta * TB + tid; i < NH; i += NCTA * TB) gh32[i] = 0u;
    }
    // x -> g_xTh [t][d48][b] fp16 (scratch = sG region)
    {
        float* scratch = sG;
        for (int t = cta; t < TT; t += NCTA) {
            __syncthreads();
            for (int i = tid; i < BB * DD; i += TB) {
                int b = i / DD, d = i - b * DD;
                scratch[b * XP + d] = x[(b * TT + t) * DD + d];
            }
            __syncthreads();
            for (int i = tid; i < XP * BB; i += TB) {
                int d = i >> 6, b = i & 63;
                g_xTh[(size_t)t * XP * BB + i] =
                    (d < DD) ? __float2half_rn(scratch[b * XP + d]) : __ushort_as_half(0);
            }
        }
    }
    __syncthreads();
    // cluster barrier: mbar inits visible before peer st.async
    asm volatile("barrier.cluster.arrive.aligned;" ::: "memory");
    asm volatile("barrier.cluster.wait.aligned;" ::: "memory");
    if (tid == 0) {
        mbar_expect_tx(smb + OFF_MB + 0, HXTX);   // filled by epilogues(1)
        mbar_expect_tx(smb + OFF_MB + 8, HXTX);   // filled by epilogues(0)
        asm volatile("fence.proxy.async;" ::: "memory");
        flag_rel(g_flag + cta * 32, base + 1);
    }
    if (tid < NCTA) {
        while (flag_acq(g_flag + tid * 32) < base + 1) { }
    }
    __syncthreads();

    const int m0 = wid * 16;
    const int ejj = tid >> 3;       // epilogue: j within slice (0..31)
    const int ebg = tid & 7;        // epilogue: batch group (8 b's)

    // ---------- main loop ----------
    for (int u = 0; u < TT; ++u) {
        // cross-layer polls (parallel lanes of warp 0)
        if (wid == 0) {
            if (lane == 0 && l > 0)
                cnt_poll(g_cnt + ((l - 1) * NSLOT + (u & (NSLOT - 1))) * 32, cnt_tgt(u));
            if (lane == 2 && l < NLAYER - 1 && u >= RS)
                cnt_poll(g_cnt + ((l + 1) * NSLOT + ((u - RS) & (NSLOT - 1))) * 32, cnt_tgt(u - RS));
        }
        __syncthreads();

        // stage x/producer rows [0, KX) via cp.async
        {
            const __half* src0 = (l == 0)
                ? (g_xTh + (size_t)u * XP * BB)
                : (g_h + (size_t)((l - 1) * RS + (u & (RS - 1))) * HP * BB);
            const int nch = KX * 8;                 // 16B chunks
            for (int i = tid; i < nch; i += TB) {
                int row = i >> 3, sub = i & 7;
                cp16(smb + OFF_X + (unsigned)(row * BS + sub * 8) * 2,
                     src0 + row * BB + sub * 8);
            }
            asm volatile("cp.async.commit_group;");
        }

        // own-h DSMEM wait + re-arm
        const unsigned hcur = (u & 1) ? OFF_H1 : OFF_H0;
        if (u >= 1) {
            mbar_wait(smb + OFF_MB + (u & 1) * 8, (unsigned)(((u - 1) >> 1) & 1));
            if (tid == 0) mbar_expect_tx(smb + OFF_MB + (u & 1) * 8, HXTX);
        }
        asm volatile("cp.async.wait_group 0;");
        __syncthreads();

        // ---- GEMM: warp w -> gate rows m0..m0+15 ----
        {
            float acc[8][4];
            #pragma unroll
            for (int jt = 0; jt < 8; ++jt)
                #pragma unroll
                for (int q = 0; q < 4; ++q) acc[jt][q] = 0.f;

            for (int c = 0; c < KC; ++c) {
                unsigned a0, a1, a2, a3;
                unsigned aaddr = smb + OFF_A +
                    (unsigned)(((m0 + (lane & 15)) * AS + c * 16 + ((lane >> 4) << 3)) * 2);
                ldsm_x4(a0, a1, a2, a3, aaddr);
                const int rloc = (c < KXc) ? c * 16 : c * 16 - KX;
                const unsigned bbase = smb + ((c < KXc) ? OFF_X : hcur);
                const unsigned brow = (unsigned)(rloc + (lane & 15));
                const unsigned bcol = (unsigned)((lane >> 4) << 3);
                #pragma unroll
                for (int jt = 0; jt < 8; jt += 2) {
                    unsigned b0, b1, b2, b3;
                    unsigned baddr = bbase + (unsigned)((brow * BS + jt * 8 + bcol) * 2);
                    ldsm_x4t(b0, b1, b2, b3, baddr);
                    mma16816(acc[jt],     a0, a1, a2, a3, b0, b1);
                    mma16816(acc[jt + 1], a0, a1, a2, a3, b2, b3);
                }
            }
            const int r = lane >> 2;
            const int q = (lane & 3) * 2;
            #pragma unroll
            for (int jt = 0; jt < 8; ++jt) {
                *(float2*)&sG[(m0 + r)     * 68 + jt * 8 + q] = make_float2(acc[jt][0], acc[jt][1]);
                *(float2*)&sG[(m0 + r + 8) * 68 + jt * 8 + q] = make_float2(acc[jt][2], acc[jt][3]);
            }
        }
        __syncthreads();

        // ---- epilogue: thread -> (ejj, 8 b's), DSMEM broadcast to 6 peers ----
        {
            // FROZEN h: global row j0+ejj of the own-h buffer (BUG FIX vs R15)
            const __half* hprev = (__half*)(smem + hcur) + (j0 + ejj) * BS + ebg * 8;
            unsigned short ho[8];
            #pragma unroll
            for (int qq = 0; qq < 8; ++qq) {
                int b = ebg * 8 + qq;
                float iv = sG[(0  + ejj) * 68 + b] + sBi[ejj];
                float fv = sG[(32 + ejj) * 68 + b] + sBi[32 + ejj];
                float gv = sG[(64 + ejj) * 68 + b] + sBi[64 + ejj];
                float ov = sG[(96 + ejj) * 68 + b] + sBi[96 + ejj];
                float co = sC[ejj * BB + b];
                float cn = sigf(fv) * co + sigf(iv) * tanhfast(gv);
                float hn = sigf(ov) * tanhfast(cn);
                bool  mm = (u < sLen[b]);
                sC[ejj * BB + b] = mm ? cn : co;
                ho[qq] = mm ? __half_as_ushort(__float2half_rn(hn))
                            : __half_as_ushort(hprev[qq]);
            }
            unsigned long long v0, v1;
            {
                unsigned w0 = (unsigned)ho[0] | ((unsigned)ho[1] << 16);
                unsigned w1 = (unsigned)ho[2] | ((unsigned)ho[3] << 16);
                unsigned w2 = (unsigned)ho[4] | ((unsigned)ho[5] << 16);
                unsigned w3 = (unsigned)ho[6] | ((unsigned)ho[7] << 16);
                v0 = (unsigned long long)w0 | ((unsigned long long)w1 << 32);
                v1 = (unsigned long long)w2 | ((unsigned long long)w3 << 32);
            }
            // DSMEM: write our 32-j slice into all 6 peers' next-parity buffer
            const unsigned hnext = ((u + 1) & 1) ? OFF_H1 : OFF_H0;
            const unsigned loff = smb + hnext + (unsigned)(((j0 + ejj) * BS + ebg * 8) * 2);
            const unsigned lmb  = smb + OFF_MB + ((u + 1) & 1) * 8;
            #pragma unroll
            for (int r = 0; r < NCOL; ++r) {
                unsigned ra = mapa_sh(loff, (unsigned)r);
                unsigned rm = mapa_sh(lmb, (unsigned)r);
                st_async64(ra, v0, rm);
                st_async64(ra + 8, v1, rm);
            }
            // cross-layer gmem h (consumers); layer 2 only needs the final step
            if (l < NLAYER - 1 || u == TT - 1) {
                __half* hout = g_h + (size_t)(l * RS + (u & (RS - 1))) * HP * BB;
                uint2* dst = (uint2*)(hout + (j0 + ejj) * BB + ebg * 8);
                dst[0] = make_uint2((unsigned)(v0 & 0xFFFFFFFFu), (unsigned)(v0 >> 32));
                dst[1] = make_uint2((unsigned)(v1 & 0xFFFFFFFFu), (unsigned)(v1 >> 32));
            }
        }
        __syncthreads();

        if (tid == 0) {
            asm volatile("fence.proxy.async;" ::: "memory");
            cnt_add(g_cnt + (l * NSLOT + (u & (NSLOT - 1))) * 32);
        }
    }

    // ---------- final FC on CTA 0 ----------
    if (cta == 0) {
        if (tid == 0) {
            const int v = TT - 1;
            cnt_poll(g_cnt + (2 * NSLOT + (v & (NSLOT - 1))) * 32, cnt_tgt(v));
        }
        __syncthreads();
        const __half* h2 = g_h + (size_t)(2 * RS + ((TT - 1) & (RS - 1))) * HP * BB;
        for (int it = tid; it < BB * NOUT; it += TB) {
            int b = it / NOUT, o = it - b * NOUT;
            float acc = fcb[o];
            for (int j = 0; j < HH; ++j) {
                unsigned short hv;
                asm volatile("ld.global.cg.u16 %0, [%1];" : "=h"(hv) : "l"(h2 + j * BB + b));
                acc += __half2float(__ushort_as_half(hv)) * fcw[o * HH + j];
            }
            out[b * NOUT + o] = acc;
        }
        __syncthreads();
    }

    if (tid == 0) flag_rel(g_flag + cta * 32, base + (unsigned)TT + 8);

    // no CTA may exit while peers' st.async to its smem could be in flight
    asm volatile("barrier.cluster.arrive.aligned;" ::: "memory");
    asm volatile("barrier.cluster.wait.aligned;" ::: "memory");
}

// ---------------- launch ----------------
extern "C" void kernel_launch(void* const* d_in, const int* in_sizes, int n_in,
                              void* d_out, int out_size) {
    const float* x       = (const float*)d_in[0];
    const int*   lengths = (const int*)  d_in[1];
    const float* Wih0    = (const float*)d_in[2];
    const float* Whh0    = (const float*)d_in[3];
    const float* b0      = (const float*)d_in[4];
    const float* Wih1    = (const float*)d_in[5];
    const float* Whh1    = (const float*)d_in[6];
    const float* b1      = (const float*)d_in[7];
    const float* Wih2    = (const float*)d_in[8];
    const float* Whh2    = (const float*)d_in[9];
    const float* b2      = (const float*)d_in[10];
    const float* fcw     = (const float*)d_in[11];
    const float* fcb     = (const float*)d_in[12];
    float* out = (float*)d_out;

    static bool attr_set = false;
    if (!attr_set) {
        cudaFuncSetAttribute(k_lstm, cudaFuncAttributeMaxDynamicSharedMemorySize, SMEM_BYTES);
        attr_set = true;
    }

    k_lstm<<<NCTA, TB, SMEM_BYTES>>>(x, lengths,
                                     Wih0, Whh0, b0,
                                     Wih1, Whh1, b1,
                                     Wih2, Whh2, b2,
                                     fcw, fcb, out);
}

// round 17
// speedup vs baseline: 2.2909x; 2.2909x over previous
#include <cuda_runtime.h>
#include <cuda_fp16.h>
#include <math.h>

// Problem constants
#define BB     64
#define TT     2048
#define DD     40
#define HH     164
#define HP     192            // padded hidden (4 j-slices x 48)
#define JS     48             // j's per CTA
#define XP     48             // padded x dim (l0)
#define BG     16             // batches per group
#define NG     4              // batch groups
#define NOUT   7
#define NCOL   4              // j-slices per (layer, bgroup) = cluster size
#define NLAYER 3
#define NCTA   48             // 3 * 4 * 4
#define TB     256            // 8 warps (6 GEMM)
#define RS     4              // cross-layer ring depth
#define NSLOT  8
#define AS     392            // A row stride (halves): 384 + 8
#define BS2    24             // B row stride (halves): 16 + 8
#define GS     20             // gates row stride (floats)
#define HXTX   6144           // DSMEM tx/phase: 4 src CTAs * 48j * 16b * 2B

// ---- smem layout (bytes) ----
#define OFF_A   0                       // weights fp16 [192][392] = 150528
#define OFF_X   150528                  // x/producer rows [192][24] = 9216
#define OFF_H0  159744                  // own-h buf0 [192][24] = 9216
#define OFF_H1  168960                  // own-h buf1 = 9216
#define OFF_G   178176                  // gates f32 [192][20] = 15360
#define OFF_C   193536                  // cell f32 [48][16] = 3072
#define OFF_BI  196608                  // bias f32 [192] = 768
#define OFF_LEN 197376                  // lengths [16] = 64
#define OFF_MB  197440                  // 2 mbarriers = 16
#define SMEM_BYTES 197456

// ---------------- device scratch ----------------
__device__ __align__(256) __half g_xTh[(size_t)TT * NG * XP * BG];      // [t][g][d48][16]
__device__ __align__(256) __half g_h[NLAYER * RS * NG * HP * BG];       // [l][slot][g][j][16]
__device__ unsigned g_flag[NCTA * 32];
__device__ __align__(128) unsigned g_cnt[NLAYER * NG * NSLOT * 32];

// ---------------- helpers ----------------
__device__ __forceinline__ unsigned smem_u32(const void* p) {
    return (unsigned)__cvta_generic_to_shared(p);
}
__device__ __forceinline__ void ldsm_x4(unsigned& r0, unsigned& r1, unsigned& r2, unsigned& r3,
                                        unsigned addr) {
    asm volatile("ldmatrix.sync.aligned.m8n8.x4.shared.b16 {%0,%1,%2,%3}, [%4];"
                 : "=r"(r0), "=r"(r1), "=r"(r2), "=r"(r3) : "r"(addr));
}
__device__ __forceinline__ void ldsm_x4t(unsigned& r0, unsigned& r1, unsigned& r2, unsigned& r3,
                                         unsigned addr) {
    asm volatile("ldmatrix.sync.aligned.m8n8.x4.trans.shared.b16 {%0,%1,%2,%3}, [%4];"
                 : "=r"(r0), "=r"(r1), "=r"(r2), "=r"(r3) : "r"(addr));
}
__device__ __forceinline__ void mma16816(float* d, unsigned a0, unsigned a1, unsigned a2,
                                         unsigned a3, unsigned b0, unsigned b1) {
    asm volatile("mma.sync.aligned.m16n8k16.row.col.f32.f16.f16.f32 "
                 "{%0,%1,%2,%3}, {%4,%5,%6,%7}, {%8,%9}, {%0,%1,%2,%3};"
                 : "+f"(d[0]), "+f"(d[1]), "+f"(d[2]), "+f"(d[3])
                 : "r"(a0), "r"(a1), "r"(a2), "r"(a3), "r"(b0), "r"(b1));
}
__device__ __forceinline__ void cp16(unsigned dst_smem, const void* src) {
    asm volatile("cp.async.cg.shared.global [%0], [%1], 16;" :: "r"(dst_smem), "l"(src));
}
__device__ __forceinline__ void mbar_init(unsigned addr, unsigned cnt) {
    asm volatile("mbarrier.init.shared.b64 [%0], %1;" :: "r"(addr), "r"(cnt) : "memory");
}
__device__ __forceinline__ void mbar_expect_tx(unsigned addr, unsigned bytes) {
    asm volatile("mbarrier.arrive.expect_tx.shared.b64 _, [%0], %1;" :: "r"(addr), "r"(bytes) : "memory");
}
__device__ __forceinline__ void mbar_wait(unsigned addr, unsigned parity) {
    asm volatile(
        "{\n\t.reg .pred P1;\n\t"
        "W_%=:\n\t"
        "mbarrier.try_wait.parity.acquire.cta.shared::cta.b64 P1, [%0], %1, 0x989680;\n\t"
        "@P1 bra D_%=;\n\tbra W_%=;\n\tD_%=:\n\t}"
        :: "r"(addr), "r"(parity) : "memory");
}
__device__ __forceinline__ unsigned mapa_sh(unsigned laddr, unsigned rank) {
    unsigned r;
    asm("mapa.shared::cluster.u32 %0, %1, %2;" : "=r"(r) : "r"(laddr), "r"(rank));
    return r;
}
__device__ __forceinline__ void st_async64(unsigned raddr, unsigned long long v, unsigned rmbar) {
    asm volatile("st.async.shared::cluster.mbarrier::complete_tx::bytes.b64 [%0], %1, [%2];"
                 :: "r"(raddr), "l"(v), "r"(rmbar) : "memory");
}
__device__ __forceinline__ unsigned flag_acq(const unsigned* p) {
    unsigned r;
    asm volatile("ld.global.acquire.gpu.u32 %0, [%1];" : "=r"(r) : "l"(p));
    return r;
}
__device__ __forceinline__ void flag_rel(unsigned* p, unsigned v) {
    asm volatile("st.global.release.gpu.u32 [%0], %1;" :: "l"(p), "r"(v) : "memory");
}
__device__ __forceinline__ void cnt_add(unsigned* p) {
    asm volatile("red.release.gpu.global.add.u32 [%0], 1;" :: "l"(p) : "memory");
}
__device__ __forceinline__ void cnt_poll(const unsigned* p, unsigned tgt) {
    while (flag_acq(p) < tgt) { }
}
__device__ __forceinline__ unsigned cnt_tgt(int v) {      // 4 arrivals per (l,g) per step
    return 4u * ((unsigned)(v >> 3) + 1u);
}
__device__ __forceinline__ float sigf(float x) {
    float e = __expf(-x);
    return __fdividef(1.f, 1.f + e);
}
__device__ __forceinline__ float tanhfast(float z) {
    float e = __expf(-2.f * z);
    return __fdividef(2.f, 1.f + e) - 1.f;
}

// ---------------- persistent HMMA LSTM, 2-D (j x batch) decomposition ----------------
__global__ void __launch_bounds__(TB, 1) __cluster_dims__(NCOL, 1, 1) k_lstm(
    const float* __restrict__ x,
    const int*   __restrict__ lengths,
    const float* __restrict__ Wih0, const float* __restrict__ Whh0, const float* __restrict__ bb0,
    const float* __restrict__ Wih1, const float* __restrict__ Whh1, const float* __restrict__ bb1,
    const float* __restrict__ Wih2, const float* __restrict__ Whh2, const float* __restrict__ bb2,
    const float* __restrict__ fcw,  const float* __restrict__ fcb,
    float* __restrict__ out)
{
    extern __shared__ char smem[];
    const unsigned smb = smem_u32(smem);
    __half* sA  = (__half*)(smem + OFF_A);
    float*  sG  = (float*)(smem + OFF_G);
    float*  sC  = (float*)(smem + OFF_C);
    float*  sBi = (float*)(smem + OFF_BI);
    int*    sLen= (int*)  (smem + OFF_LEN);

    const int tid  = threadIdx.x;
    const int cta  = blockIdx.x;
    const int l    = cta >> 4;            // cta / 16
    const int g    = (cta >> 2) & 3;      // bgroup
    const int s    = cta & 3;             // j-slice = cluster rank
    const int j0   = s * JS;
    const int wid  = tid >> 5;
    const int lane = tid & 31;

    const unsigned base = g_flag[cta * 32];

    const float *Wih, *Whh, *bias;
    int KX;
    if (l == 0)      { Wih = Wih0; Whh = Whh0; bias = bb0; KX = XP; }
    else if (l == 1) { Wih = Wih1; Whh = Whh1; bias = bb1; KX = HP; }
    else             { Wih = Wih2; Whh = Whh2; bias = bb2; KX = HP; }
    const int K   = KX + HP;              // 240 or 384
    const int KC  = K >> 4;               // 15 or 24
    const int KXc = KX >> 4;              // 3 or 12

    // ---------- Phase A ----------
    // (1) x transpose first (uses sA region as float scratch)
    {
        float* scratch = (float*)sA;      // 64*48 floats = 12.3 KB
        for (int t = cta; t < TT; t += NCTA) {
            __syncthreads();
            for (int i = tid; i < BB * XP; i += TB) {
                int b = i / XP, d = i - b * XP;
                scratch[i] = (d < DD) ? x[(b * TT + t) * DD + d] : 0.f;
            }
            __syncthreads();
            for (int i = tid; i < NG * XP * BG; i += TB) {
                int gg = i / (XP * BG);
                int r  = i - gg * (XP * BG);
                int d  = r >> 4, bb = r & 15;
                g_xTh[(size_t)t * (NG * XP * BG) + i] =
                    __float2half_rn(scratch[(gg * BG + bb) * XP + d]);
            }
        }
        __syncthreads();
    }
    // (2) weights -> sA fp16 row-major [m][k], m = gate*48 + jj
    for (int m = 0; m < 4 * JS; ++m) {
        int gt = m / JS, jj = m - gt * JS, j = j0 + jj;
        for (int k = tid; k < K; k += TB) {
            float w = 0.f;
            if (j < HH) {
                if (k < KX) {
                    if (l == 0) { if (k < DD) w = Wih[(gt * HH + j) * DD + k]; }
                    else        { if (k < HH) w = Wih[(gt * HH + j) * HH + k]; }
                } else {
                    int kk = k - KX;
                    if (kk < HH) w = Whh[(gt * HH + j) * HH + kk];
                }
            }
            sA[m * AS + k] = __float2half_rn(w);
        }
    }
    if (tid < 4 * JS) {
        int gt = tid / JS, jj = tid - gt * JS, j = j0 + jj;
        sBi[tid] = (j < HH) ? bias[gt * HH + j] : 0.f;
    }
    if (tid < BG) sLen[tid] = lengths[g * BG + tid];
    for (int i = tid; i < JS * BG; i += TB) sC[i] = 0.f;
    // zero own-h buffers + staging
    for (int i = tid; i < (3 * HP * BS2) / 2; i += TB)
        ((unsigned*)(smem + OFF_X))[i] = 0u;
    if (tid == 0) {
        mbar_init(smb + OFF_MB + 0, 1);
        mbar_init(smb + OFF_MB + 8, 1);
    }
    if (cta == 0 && tid < NLAYER * NG * NSLOT) g_cnt[tid * 32] = 0u;
    {
        unsigned* gh32 = (unsigned*)g_h;
        const int NH = (NLAYER * RS * NG * HP * BG) / 2;
        for (int i = cta * TB + tid; i < NH; i += NCTA * TB) gh32[i] = 0u;
    }
    __syncthreads();
    // cluster barrier: mbar inits visible before peer st.async
    asm volatile("barrier.cluster.arrive.aligned;" ::: "memory");
    asm volatile("barrier.cluster.wait.aligned;" ::: "memory");
    if (tid == 0) {
        mbar_expect_tx(smb + OFF_MB + 0, HXTX);
        mbar_expect_tx(smb + OFF_MB + 8, HXTX);
        asm volatile("fence.proxy.async;" ::: "memory");
        flag_rel(g_flag + cta * 32, base + 1);
    }
    if (tid < NCTA) {
        while (flag_acq(g_flag + tid * 32) < base + 1) { }
    }
    __syncthreads();

    const int m0w = wid * 32;             // warps 0..5: 32 gate-rows each

    // ---------- main loop ----------
    for (int u = 0; u < TT; ++u) {
        // cross-layer polls (warp 6, parallel lanes)
        if (tid == 192 && l > 0)
            cnt_poll(g_cnt + (((l - 1) * NG + g) * NSLOT + (u & 7)) * 32, cnt_tgt(u));
        if (tid == 193 && l < NLAYER - 1 && u >= RS)
            cnt_poll(g_cnt + (((l + 1) * NG + g) * NSLOT + ((u - RS) & 7)) * 32, cnt_tgt(u - RS));
        __syncthreads();

        // stage x/producer rows [0, KX) via cp.async (32B per row = 2 x 16B)
        {
            const __half* src0 = (l == 0)
                ? (g_xTh + (size_t)u * (NG * XP * BG) + g * (XP * BG))
                : (g_h + (size_t)(((l - 1) * RS + (u & 3)) * NG + g) * HP * BG);
            const int nch = KX * 2;
            for (int i = tid; i < nch; i += TB) {
                int row = i >> 1, sub = i & 1;
                cp16(smb + OFF_X + (unsigned)(row * BS2 + sub * 8) * 2,
                     src0 + row * BG + sub * 8);
            }
            asm volatile("cp.async.commit_group;");
        }

        // own-h DSMEM wait + re-arm (R16-proven protocol)
        const unsigned hcur = (u & 1) ? OFF_H1 : OFF_H0;
        if (u >= 1) {
            mbar_wait(smb + OFF_MB + (u & 1) * 8, (unsigned)(((u - 1) >> 1) & 1));
            if (tid == 0) mbar_expect_tx(smb + OFF_MB + (u & 1) * 8, HXTX);
        }
        asm volatile("cp.async.wait_group 0;");
        __syncthreads();

        // ---- GEMM: warps 0-5, each 32 gate-rows (2 m-tiles), N=16 ----
        if (wid < 6) {
            float acc[2][2][4];
            #pragma unroll
            for (int mt = 0; mt < 2; ++mt)
                #pragma unroll
                for (int nt = 0; nt < 2; ++nt)
                    #pragma unroll
                    for (int q = 0; q < 4; ++q) acc[mt][nt][q] = 0.f;

            const unsigned bcol = (unsigned)((lane >> 4) << 3);
            for (int c = 0; c < KC; ++c) {
                const int rloc = (c < KXc) ? c * 16 : c * 16 - KX;
                const unsigned bbase = smb + ((c < KXc) ? OFF_X : hcur);
                unsigned b0, b1, b2, b3;
                unsigned baddr = bbase +
                    (unsigned)(((rloc + (lane & 15)) * BS2 + bcol) * 2);
                ldsm_x4t(b0, b1, b2, b3, baddr);
                #pragma unroll
                for (int mt = 0; mt < 2; ++mt) {
                    unsigned a0, a1, a2, a3;
                    unsigned aaddr = smb + OFF_A +
                        (unsigned)(((m0w + mt * 16 + (lane & 15)) * AS + c * 16 + bcol) * 2);
                    ldsm_x4(a0, a1, a2, a3, aaddr);
                    mma16816(acc[mt][0], a0, a1, a2, a3, b0, b1);
                    mma16816(acc[mt][1], a0, a1, a2, a3, b2, b3);
                }
            }
            const int r = lane >> 2;
            const int q = (lane & 3) * 2;
            #pragma unroll
            for (int mt = 0; mt < 2; ++mt) {
                int row = m0w + mt * 16 + r;
                *(float2*)&sG[row * GS + q]           = make_float2(acc[mt][0][0], acc[mt][0][1]);
                *(float2*)&sG[(row + 8) * GS + q]     = make_float2(acc[mt][0][2], acc[mt][0][3]);
                *(float2*)&sG[row * GS + 8 + q]       = make_float2(acc[mt][1][0], acc[mt][1][1]);
                *(float2*)&sG[(row + 8) * GS + 8 + q] = make_float2(acc[mt][1][2], acc[mt][1][3]);
            }
        }
        __syncthreads();

        // ---- epilogue: tid<192, thread -> (ejj, 4 b's) ----
        if (tid < 192) {
            const int ejj = tid >> 2;
            const int ebg = tid & 3;
            const __half* hprev = (__half*)(smem + hcur) + (j0 + ejj) * BS2 + ebg * 4;
            unsigned short ho[4];
            #pragma unroll
            for (int qq = 0; qq < 4; ++qq) {
                int b = ebg * 4 + qq;
                float iv = sG[(0   + ejj) * GS + b] + sBi[ejj];
                float fv = sG[(48  + ejj) * GS + b] + sBi[48 + ejj];
                float gv = sG[(96  + ejj) * GS + b] + sBi[96 + ejj];
                float ov = sG[(144 + ejj) * GS + b] + sBi[144 + ejj];
                float co = sC[ejj * BG + b];
                float cn = sigf(fv) * co + sigf(iv) * tanhfast(gv);
                float hn = sigf(ov) * tanhfast(cn);
                bool  mm = (u < sLen[b]);
                sC[ejj * BG + b] = mm ? cn : co;
                ho[qq] = mm ? __half_as_ushort(__float2half_rn(hn))
                            : __half_as_ushort(hprev[qq]);
            }
            unsigned w0 = (unsigned)ho[0] | ((unsigned)ho[1] << 16);
            unsigned w1 = (unsigned)ho[2] | ((unsigned)ho[3] << 16);
            unsigned long long v0 = (unsigned long long)w0 | ((unsigned long long)w1 << 32);

            // DSMEM: write our (j, 4b) word into all 4 j-partners' next buffer
            const unsigned hnext = ((u + 1) & 1) ? OFF_H1 : OFF_H0;
            const unsigned loff = smb + hnext + (unsigned)(((j0 + ejj) * BS2 + ebg * 4) * 2);
            const unsigned lmb  = smb + OFF_MB + ((u + 1) & 1) * 8;
            #pragma unroll
            for (int r = 0; r < NCOL; ++r) {
                st_async64(mapa_sh(loff, (unsigned)r), v0, mapa_sh(lmb, (unsigned)r));
            }
            // cross-layer gmem publish (layer 2 only needs the final step)
            if (l < NLAYER - 1 || u == TT - 1) {
                __half* dst = g_h + (size_t)((l * RS + (u & 3)) * NG + g) * HP * BG
                              + (j0 + ejj) * BG + ebg * 4;
                *(uint2*)dst = make_uint2(w0, w1);
            }
        }
        __syncthreads();

        if (tid == 0) {
            asm volatile("fence.proxy.async;" ::: "memory");
            cnt_add(g_cnt + ((l * NG + g) * NSLOT + (u & 7)) * 32);
        }
    }

    // ---------- final FC on CTA 0 ----------
    if (cta == 0) {
        if (tid < NG) {
            const int v = TT - 1;
            cnt_poll(g_cnt + ((2 * NG + tid) * NSLOT + (v & 7)) * 32, cnt_tgt(v));
        }
        __syncthreads();
        for (int it = tid; it < BB * NOUT; it += TB) {
            int b = it / NOUT, o = it - b * NOUT;
            const size_t hb = (size_t)((2 * RS + ((TT - 1) & 3)) * NG + (b >> 4)) * HP * BG
                              + (b & 15);
            float acc = fcb[o];
            for (int j = 0; j < HH; ++j) {
                unsigned short hv;
                asm volatile("ld.global.cg.u16 %0, [%1];" : "=h"(hv) : "l"(g_h + hb + j * BG));
                acc += __half2float(__ushort_as_half(hv)) * fcw[o * HH + j];
            }
            out[b * NOUT + o] = acc;
        }
        __syncthreads();
    }

    if (tid == 0) flag_rel(g_flag + cta * 32, base + (unsigned)TT + 8);

    // no CTA may exit while peers' st.async to its smem could be in flight
    asm volatile("barrier.cluster.arrive.aligned;" ::: "memory");
    asm volatile("barrier.cluster.wait.aligned;" ::: "memory");
}

// ---------------- launch ----------------
extern "C" void kernel_launch(void* const* d_in, const int* in_sizes, int n_in,
                              void* d_out, int out_size) {
    const float* x       = (const float*)d_in[0];
    const int*   lengths = (const int*)  d_in[1];
    const float* Wih0    = (const float*)d_in[2];
    const float* Whh0    = (const float*)d_in[3];
    const float* b0      = (const float*)d_in[4];
    const float* Wih1    = (const float*)d_in[5];
    const float* Whh1    = (const float*)d_in[6];
    const float* b1      = (const float*)d_in[7];
    const float* Wih2    = (const float*)d_in[8];
    const float* Whh2    = (const float*)d_in[9];
    const float* b2      = (const float*)d_in[10];
    const float* fcw     = (const float*)d_in[11];
    const float* fcb     = (const float*)d_in[12];
    float* out = (float*)d_out;

    static bool attr_set = false;
    if (!attr_set) {
        cudaFuncSetAttribute(k_lstm, cudaFuncAttributeMaxDynamicSharedMemorySize, SMEM_BYTES);
        attr_set = true;
    }

    k_lstm<<<NCTA, TB, SMEM_BYTES>>>(x, lengths,
                                     Wih0, Whh0, b0,
                                     Wih1, Whh1, b1,
                                     Wih2, Whh2, b2,
                                     fcw, fcb, out);
}